// round 3
// baseline (speedup 1.0000x reference)
#include <cuda_runtime.h>

// Partial sums scratch: one float per block of the reduce kernel.
// Static __device__ array — no allocation, graph-capture safe.
#define MAX_BLOCKS 4096
__device__ float g_partials[MAX_BLOCKS];

// Kernel 1: grid-stride vectorized dot-product partial reduction.
// acc[n-chunk] = sum(feats .* warped) over this thread's slice.
__global__ void __launch_bounds__(256)
cosdist_dot_kernel(const float4* __restrict__ a,
                   const float4* __restrict__ b,
                   long long n4)
{
    float acc = 0.0f;
    long long i      = (long long)blockIdx.x * blockDim.x + threadIdx.x;
    long long stride = (long long)gridDim.x * blockDim.x;

    // 2-way unrolled grid-stride loop: 4 outstanding LDG.128 per iteration
    // for memory-level parallelism.
    for (; i + stride < n4; i += 2 * stride) {
        float4 x0 = a[i];
        float4 y0 = b[i];
        float4 x1 = a[i + stride];
        float4 y1 = b[i + stride];
        acc = fmaf(x0.x, y0.x, acc);
        acc = fmaf(x0.y, y0.y, acc);
        acc = fmaf(x0.z, y0.z, acc);
        acc = fmaf(x0.w, y0.w, acc);
        acc = fmaf(x1.x, y1.x, acc);
        acc = fmaf(x1.y, y1.y, acc);
        acc = fmaf(x1.z, y1.z, acc);
        acc = fmaf(x1.w, y1.w, acc);
    }
    if (i < n4) {
        float4 x = a[i];
        float4 y = b[i];
        acc = fmaf(x.x, y.x, acc);
        acc = fmaf(x.y, y.y, acc);
        acc = fmaf(x.z, y.z, acc);
        acc = fmaf(x.w, y.w, acc);
    }

    // Warp reduce
    #pragma unroll
    for (int off = 16; off > 0; off >>= 1)
        acc += __shfl_down_sync(0xFFFFFFFF, acc, off);

    __shared__ float s_warp[8];  // 256 threads = 8 warps
    int lane = threadIdx.x & 31;
    int wid  = threadIdx.x >> 5;
    if (lane == 0) s_warp[wid] = acc;
    __syncthreads();

    // First warp reduces the 8 warp partials
    if (wid == 0) {
        float v = (lane < 8) ? s_warp[lane] : 0.0f;
        #pragma unroll
        for (int off = 4; off > 0; off >>= 1)
            v += __shfl_down_sync(0xFFFFFFFF, v, off);
        if (lane == 0) g_partials[blockIdx.x] = v;
    }
}

// Kernel 2: single block reduces all block partials; out = 1 - sum/N.
__global__ void __launch_bounds__(1024)
cosdist_finalize_kernel(float* __restrict__ out, int nblocks, float invN)
{
    float acc = 0.0f;
    for (int i = threadIdx.x; i < nblocks; i += blockDim.x)
        acc += g_partials[i];

    #pragma unroll
    for (int off = 16; off > 0; off >>= 1)
        acc += __shfl_down_sync(0xFFFFFFFF, acc, off);

    __shared__ float s_warp[32];  // 1024 threads = 32 warps
    int lane = threadIdx.x & 31;
    int wid  = threadIdx.x >> 5;
    if (lane == 0) s_warp[wid] = acc;
    __syncthreads();

    if (wid == 0) {
        float v = (lane < 32) ? s_warp[lane] : 0.0f;
        #pragma unroll
        for (int off = 16; off > 0; off >>= 1)
            v += __shfl_down_sync(0xFFFFFFFF, v, off);
        if (lane == 0) out[0] = 1.0f - v * invN;
    }
}

extern "C" void kernel_launch(void* const* d_in, const int* in_sizes, int n_in,
                              void* d_out, int out_size)
{
    const float* feats  = (const float*)d_in[0];   // [D=512, N=65536] fp32
    const float* warped = (const float*)d_in[1];   // [D=512, N=65536] fp32
    float* out = (float*)d_out;                    // scalar fp32

    long long total = (long long)in_sizes[0];      // 512 * 65536 = 33,554,432
    long long n4    = total >> 2;                  // 8,388,608 float4 pairs

    const int threads = 256;
    int blocks = 1184;                             // 8 blocks/SM * 148 SMs
    if (blocks > MAX_BLOCKS) blocks = MAX_BLOCKS;

    // N = 65536 columns; mean over N of (1 - diag[n]) = 1 - total_dot / N
    const float invN = 1.0f / 65536.0f;

    cosdist_dot_kernel<<<blocks, threads>>>(
        (const float4*)feats, (const float4*)warped, n4);
    cosdist_finalize_kernel<<<1, 1024>>>(out, blocks, invN);
}